// round 2
// baseline (speedup 1.0000x reference)
#include <cuda_runtime.h>
#include <cuda_bf16.h>
#include <cstdint>

// Problem constants (fixed by the reference)
#define NN 50000
#define EE 800000
#define HH 4
#define DD 32
#define INF_ 128   // in_feats = H*D = 128

// ---------------- scratch (static device globals; no allocs allowed) -------
__device__ float g_q [NN * INF_];
__device__ float g_k [NN * INF_];
__device__ float g_v [NN * INF_];
__device__ float g_ft[NN * INF_];
__device__ float g_ex[EE * HH];
__device__ float g_weff[INF_ * INF_];
__device__ int   g_cnt[NN];
__device__ int   g_off[NN + 1];
__device__ int   g_cur[NN];
__device__ int   g_esrc[EE];

// ---------------- small init kernels ---------------------------------------
__global__ void zero_cnt_k() {
    int i = blockIdx.x * blockDim.x + threadIdx.x;
    if (i < NN) g_cnt[i] = 0;
}

// Weff[i][j] = sum_h Wscale[h*128 + i][j]   (fold head-sum into the weight)
__global__ void weff_k(const float* __restrict__ Wscale) {
    int idx = blockIdx.x * blockDim.x + threadIdx.x;
    if (idx < INF_ * INF_) {
        int i = idx >> 7, j = idx & 127;
        float s = 0.f;
#pragma unroll
        for (int h = 0; h < HH; h++)
            s += Wscale[(h * 128 + i) * 128 + j];
        g_weff[idx] = s;
    }
}

// ---------------- CSR build ------------------------------------------------
__global__ void hist_k(const int* __restrict__ dst) {
    int e = blockIdx.x * blockDim.x + threadIdx.x;
    if (e < EE) atomicAdd(&g_cnt[dst[e]], 1);
}

// single-block exclusive scan over g_cnt -> g_off, g_cur
__global__ void scan_k() {
    __shared__ int sums[1024];
    int tid = threadIdx.x;
    const int chunk = (NN + 1023) / 1024;
    int base = tid * chunk;
    int s = 0;
    for (int i = 0; i < chunk; i++) {
        int idx = base + i;
        if (idx < NN) s += g_cnt[idx];
    }
    sums[tid] = s;
    __syncthreads();
    // Hillis-Steele inclusive scan
    for (int d = 1; d < 1024; d <<= 1) {
        int v = (tid >= d) ? sums[tid - d] : 0;
        __syncthreads();
        sums[tid] += v;
        __syncthreads();
    }
    int run = (tid == 0) ? 0 : sums[tid - 1];
    for (int i = 0; i < chunk; i++) {
        int idx = base + i;
        if (idx < NN) {
            g_off[idx] = run;
            g_cur[idx] = run;
            run += g_cnt[idx];
        }
    }
    if (tid == 0) g_off[NN] = sums[1023];
}

__global__ void scatter_k(const int* __restrict__ src, const int* __restrict__ dst) {
    int e = blockIdx.x * blockDim.x + threadIdx.x;
    if (e < EE) {
        int d = dst[e];
        int p = atomicAdd(&g_cur[d], 1);
        g_esrc[p] = src[e];
    }
}

// ---------------- SIMT fp32 GEMM: C = A(MxK) @ B(NxK)^T [+ Res] ------------
#define BM 64
#define BN 64
#define BK 32
__global__ __launch_bounds__(256) void gemm_tn_k(
    const float* __restrict__ A, const float* __restrict__ B,
    const float* __restrict__ Res, float* __restrict__ C,
    int M, int Nn, int K)
{
    __shared__ float As[BK][BM + 4];
    __shared__ float Bs[BK][BN + 4];
    int tid = threadIdx.x;
    int tx = tid & 15, ty = tid >> 4;
    int m0 = blockIdx.x * BM;
    int n0 = blockIdx.y * BN;
    float acc[4][4] = {};

    for (int kk = 0; kk < K; kk += BK) {
        for (int t = tid; t < BM * (BK / 4); t += 256) {
            int r = t / (BK / 4);
            int c4 = t % (BK / 4);
            float4 va = make_float4(0.f, 0.f, 0.f, 0.f);
            int gm = m0 + r;
            if (gm < M) va = *(const float4*)(A + (size_t)gm * K + kk + c4 * 4);
            As[c4 * 4 + 0][r] = va.x; As[c4 * 4 + 1][r] = va.y;
            As[c4 * 4 + 2][r] = va.z; As[c4 * 4 + 3][r] = va.w;
        }
        for (int t = tid; t < BN * (BK / 4); t += 256) {
            int r = t / (BK / 4);
            int c4 = t % (BK / 4);
            float4 vb = make_float4(0.f, 0.f, 0.f, 0.f);
            int gn = n0 + r;
            if (gn < Nn) vb = *(const float4*)(B + (size_t)gn * K + kk + c4 * 4);
            Bs[c4 * 4 + 0][r] = vb.x; Bs[c4 * 4 + 1][r] = vb.y;
            Bs[c4 * 4 + 2][r] = vb.z; Bs[c4 * 4 + 3][r] = vb.w;
        }
        __syncthreads();
#pragma unroll
        for (int k = 0; k < BK; k++) {
            float4 a4 = *(const float4*)&As[k][ty * 4];
            float4 b4 = *(const float4*)&Bs[k][tx * 4];
            float a[4] = {a4.x, a4.y, a4.z, a4.w};
            float b[4] = {b4.x, b4.y, b4.z, b4.w};
#pragma unroll
            for (int i = 0; i < 4; i++)
#pragma unroll
                for (int j = 0; j < 4; j++)
                    acc[i][j] += a[i] * b[j];
        }
        __syncthreads();
    }
#pragma unroll
    for (int i = 0; i < 4; i++) {
        int gm = m0 + ty * 4 + i;
        if (gm >= M) continue;
#pragma unroll
        for (int j = 0; j < 4; j++) {
            int gn = n0 + tx * 4 + j;
            if (gn >= Nn) continue;
            float r = acc[i][j];
            if (Res) r += Res[(size_t)gm * Nn + gn];
            C[(size_t)gm * Nn + gn] = r;
        }
    }
}

// ---------------- fused score + edge-softmax + aggregate (warp per dst) ----
__global__ void agg_k() {
    int n = (blockIdx.x * blockDim.x + threadIdx.x) >> 5;
    if (n >= NN) return;
    int lane = threadIdx.x & 31;
    int h = lane >> 3;

    int beg = g_off[n], end = g_off[n + 1];
    float4 kreg = ((const float4*)(g_k + (size_t)n * INF_))[lane];

    const float scale = 0.17677669529663689f;  // 1/sqrt(32)
    float den = 0.f;
    for (int j = beg; j < end; j++) {
        int s = g_esrc[j];
        float4 qa = ((const float4*)(g_q + (size_t)s * INF_))[lane];
        float p = qa.x * kreg.x + qa.y * kreg.y + qa.z * kreg.z + qa.w * kreg.w;
        p += __shfl_xor_sync(0xFFFFFFFFu, p, 4);
        p += __shfl_xor_sync(0xFFFFFFFFu, p, 2);
        p += __shfl_xor_sync(0xFFFFFFFFu, p, 1);
        float exv = __expf(p * scale);   // no max-shift: |score| bounded (~7)
        den += exv;                      // identical within each 8-lane head group
        if ((lane & 7) == 0) g_ex[(size_t)j * HH + h] = exv;
    }
    float inv = (end > beg) ? 1.f / den : 0.f;

    float4 acc = make_float4(0.f, 0.f, 0.f, 0.f);
    for (int j = beg; j < end; j++) {
        int s = g_esrc[j];
        float a = g_ex[(size_t)j * HH + h] * inv;
        float4 vv = ((const float4*)(g_v + (size_t)s * INF_))[lane];
        acc.x += a * vv.x; acc.y += a * vv.y;
        acc.z += a * vv.z; acc.w += a * vv.w;
    }
    ((float4*)(g_ft + (size_t)n * INF_))[lane] = acc;
}

// ---------------- launch ---------------------------------------------------
extern "C" void kernel_launch(void* const* d_in, const int* in_sizes, int n_in,
                              void* d_out, int out_size) {
    const float* feature = (const float*)d_in[0];
    const float* Wq      = (const float*)d_in[1];
    const float* Wk      = (const float*)d_in[2];
    const float* Wv      = (const float*)d_in[3];
    const float* Wscale  = (const float*)d_in[4];
    const int*   src     = (const int*)d_in[5];
    const int*   dst     = (const int*)d_in[6];
    float* out = (float*)d_out;

    // One-time symbol address resolution (not a stream op; cached to keep the
    // capture path free of any runtime-API noise).
    static float *pq = nullptr, *pk, *pv, *pft, *pweff;
    if (!pq) {
        cudaGetSymbolAddress((void**)&pq, g_q);
        cudaGetSymbolAddress((void**)&pk, g_k);
        cudaGetSymbolAddress((void**)&pv, g_v);
        cudaGetSymbolAddress((void**)&pft, g_ft);
        cudaGetSymbolAddress((void**)&pweff, g_weff);
    }

    // init
    zero_cnt_k<<<(NN + 255) / 256, 256>>>();
    weff_k<<<(INF_ * INF_ + 255) / 256, 256>>>(Wscale);

    // projections: q/k/v = feature @ W^T
    dim3 gq((NN + BM - 1) / BM, INF_ / BN);
    gemm_tn_k<<<gq, 256>>>(feature, Wq, nullptr, pq, NN, INF_, INF_);
    gemm_tn_k<<<gq, 256>>>(feature, Wk, nullptr, pk, NN, INF_, INF_);
    gemm_tn_k<<<gq, 256>>>(feature, Wv, nullptr, pv, NN, INF_, INF_);

    // CSR by destination
    hist_k<<<(EE + 255) / 256, 256>>>(dst);
    scan_k<<<1, 1024>>>();
    scatter_k<<<(EE + 255) / 256, 256>>>(src, dst);

    // fused edge softmax + aggregation (warp per destination node)
    agg_k<<<(NN * 32 + 255) / 256, 256>>>();

    // out = ft @ Weff^T + feature
    gemm_tn_k<<<gq, 256>>>(pft, pweff, feature, out, NN, INF_, INF_);
}

// round 4
// speedup vs baseline: 1.2173x; 1.2173x over previous
#include <cuda_runtime.h>
#include <cuda_bf16.h>
#include <cstdint>

#define NN 50000
#define EE 800000
#define HH 4
#define INF_ 128

// ---------------- scratch ---------------------------------------------------
__device__ float g_q [NN * INF_];
__device__ float g_k [NN * INF_];
__device__ float g_v [NN * INF_];
__device__ float g_ft[NN * INF_];
__device__ float g_weff[INF_ * INF_];
__device__ int   g_cnt[NN];
__device__ int   g_off[NN + 1];
__device__ int   g_cur[NN];
__device__ int   g_esrc[EE];

// ---------------- mma.sync bf16 GEMM ----------------------------------------
// C(Mx128) = A(Mx128) @ W(128x128)^T [+Res], fp32 in/out via bf16 hi/lo split.
// Block: 128x128 tile, 256 threads / 8 warps, warp tile 32x64.
// smem planes (bf16, row stride 136 => 4-bank rotation per row, conflict-free):
#define RS 136                      // row stride in bf16 elems
#define PLANE_B (128 * RS * 2)      // 34816 bytes per plane
#define A_HI 0
#define A_LO (PLANE_B)
#define B_HI (2 * PLANE_B)
#define B_LO (3 * PLANE_B)
#define SM_NEED (4 * PLANE_B)       // 139264 B

__device__ __forceinline__ void mma16816(float* d, uint32_t a0, uint32_t a1,
                                         uint32_t a2, uint32_t a3,
                                         uint32_t b0, uint32_t b1) {
    asm volatile(
        "mma.sync.aligned.m16n8k16.row.col.f32.bf16.bf16.f32 "
        "{%0,%1,%2,%3}, {%4,%5,%6,%7}, {%8,%9}, {%0,%1,%2,%3};"
        : "+f"(d[0]), "+f"(d[1]), "+f"(d[2]), "+f"(d[3])
        : "r"(a0), "r"(a1), "r"(a2), "r"(a3), "r"(b0), "r"(b1));
}

__device__ __forceinline__ void split4(float4 x, uint2& hv, uint2& lv) {
    __nv_bfloat16 h0 = __float2bfloat16(x.x), h1 = __float2bfloat16(x.y);
    __nv_bfloat16 h2 = __float2bfloat16(x.z), h3 = __float2bfloat16(x.w);
    __nv_bfloat16 l0 = __float2bfloat16(x.x - __bfloat162float(h0));
    __nv_bfloat16 l1 = __float2bfloat16(x.y - __bfloat162float(h1));
    __nv_bfloat16 l2 = __float2bfloat16(x.z - __bfloat162float(h2));
    __nv_bfloat16 l3 = __float2bfloat16(x.w - __bfloat162float(h3));
    hv.x = (uint32_t)__bfloat16_as_ushort(h0) | ((uint32_t)__bfloat16_as_ushort(h1) << 16);
    hv.y = (uint32_t)__bfloat16_as_ushort(h2) | ((uint32_t)__bfloat16_as_ushort(h3) << 16);
    lv.x = (uint32_t)__bfloat16_as_ushort(l0) | ((uint32_t)__bfloat16_as_ushort(l1) << 16);
    lv.y = (uint32_t)__bfloat16_as_ushort(l2) | ((uint32_t)__bfloat16_as_ushort(l3) << 16);
}

__global__ __launch_bounds__(256) void mma_gemm_k(
    const float* __restrict__ A, const float* __restrict__ W,
    const float* __restrict__ Res, float* __restrict__ C, int M)
{
    extern __shared__ char sm[];
    int tid = threadIdx.x, lane = tid & 31, wid = tid >> 5;
    int m0 = blockIdx.x * 128;

    // ---- stage A and W tiles as bf16 hi/lo planes ----
    {
        int row = tid >> 1, half = tid & 1;           // 2 threads per row
        bool valid = (m0 + row) < M;
        const float* arow = A + (size_t)(m0 + row) * 128 + half * 64;
        const float* wrow = W + (size_t)row * 128 + half * 64;
        uint32_t soff = (uint32_t)(row * RS + half * 64) * 2;  // bytes
#pragma unroll
        for (int i = 0; i < 16; i++) {
            float4 xa = valid ? *(const float4*)(arow + i * 4)
                              : make_float4(0.f, 0.f, 0.f, 0.f);
            uint2 hv, lv;
            split4(xa, hv, lv);
            *(uint2*)(sm + A_HI + soff + i * 8) = hv;
            *(uint2*)(sm + A_LO + soff + i * 8) = lv;
            float4 xw = *(const float4*)(wrow + i * 4);
            split4(xw, hv, lv);
            *(uint2*)(sm + B_HI + soff + i * 8) = hv;
            *(uint2*)(sm + B_LO + soff + i * 8) = lv;
        }
    }
    __syncthreads();

    // ---- warp tiling: warp (wm, wn) owns rows wm*32..+31, cols wn*64..+63 ----
    int wm = wid & 3, wn = wid >> 2;
    float acc[2][8][4];
#pragma unroll
    for (int mt = 0; mt < 2; mt++)
#pragma unroll
        for (int nt = 0; nt < 8; nt++)
#pragma unroll
            for (int i = 0; i < 4; i++) acc[mt][nt][i] = 0.f;

    const uint32_t* smw = (const uint32_t*)sm;     // word view (RS/2=68 words/row)
    int arow0 = wm * 32 + (lane >> 2);             // fragment base row (A)
    int brow0 = wn * 64 + (lane >> 2);             // fragment base row (B = out col)
    int kword = lane & 3;                          // (lane%4) word within k-chunk

    // plane pairs: (Ahi,Bhi), (Ahi,Blo), (Alo,Bhi)
    const int APL[3] = {A_HI / 4, A_HI / 4, A_LO / 4};
    const int BPL[3] = {B_HI / 4, B_LO / 4, B_HI / 4};

#pragma unroll
    for (int p = 0; p < 3; p++) {
        const uint32_t* ap = smw + APL[p];
        const uint32_t* bp = smw + BPL[p];
#pragma unroll
        for (int k0 = 0; k0 < 8; k0++) {
            int kbase = k0 * 8 + kword;
            uint32_t bf[8][2];
#pragma unroll
            for (int nt = 0; nt < 8; nt++) {
                int bi = (brow0 + nt * 8) * 68 + kbase;
                bf[nt][0] = bp[bi];
                bf[nt][1] = bp[bi + 4];
            }
#pragma unroll
            for (int mt = 0; mt < 2; mt++) {
                int ai = (arow0 + mt * 16) * 68 + kbase;
                uint32_t a0 = ap[ai];
                uint32_t a1 = ap[ai + 8 * 68];
                uint32_t a2 = ap[ai + 4];
                uint32_t a3 = ap[ai + 8 * 68 + 4];
#pragma unroll
                for (int nt = 0; nt < 8; nt++)
                    mma16816(acc[mt][nt], a0, a1, a2, a3, bf[nt][0], bf[nt][1]);
            }
        }
    }

    // ---- epilogue: direct register -> gmem (float2 per fragment row) ----
    int crow = m0 + wm * 32 + (lane >> 2);
    int ccol0 = wn * 64 + (lane & 3) * 2;
#pragma unroll
    for (int mt = 0; mt < 2; mt++) {
#pragma unroll
        for (int half = 0; half < 2; half++) {      // c0c1 (row), c2c3 (row+8)
            int gm = crow + mt * 16 + half * 8;
            if (gm >= M) continue;
#pragma unroll
            for (int nt = 0; nt < 8; nt++) {
                float2 v = make_float2(acc[mt][nt][half * 2],
                                       acc[mt][nt][half * 2 + 1]);
                size_t gi = (size_t)gm * 128 + ccol0 + nt * 8;
                if (Res) {
                    float2 r = *(const float2*)(Res + gi);
                    v.x += r.x; v.y += r.y;
                }
                *(float2*)(C + gi) = v;
            }
        }
    }
}

// ---------------- small init kernels ---------------------------------------
__global__ void zero_cnt_k() {
    int i = blockIdx.x * blockDim.x + threadIdx.x;
    if (i < NN) g_cnt[i] = 0;
}
__global__ void weff_k(const float* __restrict__ Wscale) {
    int idx = blockIdx.x * blockDim.x + threadIdx.x;
    if (idx < INF_ * INF_) {
        int i = idx >> 7, j = idx & 127;
        float s = 0.f;
#pragma unroll
        for (int h = 0; h < HH; h++)
            s += Wscale[(h * 128 + i) * 128 + j];
        g_weff[idx] = s;
    }
}

// ---------------- CSR build ------------------------------------------------
__global__ void hist_k(const int* __restrict__ dst) {
    int e = blockIdx.x * blockDim.x + threadIdx.x;
    if (e < EE) atomicAdd(&g_cnt[dst[e]], 1);
}
__global__ void scan_k() {
    __shared__ int sums[1024];
    int tid = threadIdx.x;
    const int chunk = (NN + 1023) / 1024;
    int base = tid * chunk;
    int s = 0;
    for (int i = 0; i < chunk; i++) {
        int idx = base + i;
        if (idx < NN) s += g_cnt[idx];
    }
    sums[tid] = s;
    __syncthreads();
    for (int d = 1; d < 1024; d <<= 1) {
        int v = (tid >= d) ? sums[tid - d] : 0;
        __syncthreads();
        sums[tid] += v;
        __syncthreads();
    }
    int run = (tid == 0) ? 0 : sums[tid - 1];
    for (int i = 0; i < chunk; i++) {
        int idx = base + i;
        if (idx < NN) {
            g_off[idx] = run;
            g_cur[idx] = run;
            run += g_cnt[idx];
        }
    }
    if (tid == 0) g_off[NN] = sums[1023];
}
__global__ void scatter_k(const int* __restrict__ src, const int* __restrict__ dst) {
    int e = blockIdx.x * blockDim.x + threadIdx.x;
    if (e < EE) {
        int d = dst[e];
        int p = atomicAdd(&g_cur[d], 1);
        g_esrc[p] = src[e];
    }
}

// ---------------- fused single-pass score + softmax + aggregate ------------
__global__ void agg_k() {
    int n = (blockIdx.x * blockDim.x + threadIdx.x) >> 5;
    if (n >= NN) return;
    int lane = threadIdx.x & 31;

    int beg = g_off[n], end = g_off[n + 1];
    float4 kreg = ((const float4*)(g_k + (size_t)n * INF_))[lane];

    const float scale = 0.17677669529663689f;  // 1/sqrt(32)
    float den = 0.f;
    float4 acc = make_float4(0.f, 0.f, 0.f, 0.f);
    for (int j = beg; j < end; j++) {
        int s = g_esrc[j];
        float4 qa = ((const float4*)(g_q + (size_t)s * INF_))[lane];
        float4 vv = ((const float4*)(g_v + (size_t)s * INF_))[lane];
        float p = qa.x * kreg.x + qa.y * kreg.y + qa.z * kreg.z + qa.w * kreg.w;
        p += __shfl_xor_sync(0xFFFFFFFFu, p, 4);
        p += __shfl_xor_sync(0xFFFFFFFFu, p, 2);
        p += __shfl_xor_sync(0xFFFFFFFFu, p, 1);
        float e = __expf(p * scale);   // per-head value, same across 8-lane group
        den += e;
        acc.x += e * vv.x; acc.y += e * vv.y;
        acc.z += e * vv.z; acc.w += e * vv.w;
    }
    float inv = (end > beg) ? 1.f / den : 0.f;
    acc.x *= inv; acc.y *= inv; acc.z *= inv; acc.w *= inv;
    ((float4*)(g_ft + (size_t)n * INF_))[lane] = acc;
}

// ---------------- launch ---------------------------------------------------
extern "C" void kernel_launch(void* const* d_in, const int* in_sizes, int n_in,
                              void* d_out, int out_size) {
    const float* feature = (const float*)d_in[0];
    const float* Wq      = (const float*)d_in[1];
    const float* Wk      = (const float*)d_in[2];
    const float* Wv      = (const float*)d_in[3];
    const float* Wscale  = (const float*)d_in[4];
    const int*   src     = (const int*)d_in[5];
    const int*   dst     = (const int*)d_in[6];
    float* out = (float*)d_out;

    static float *pq = nullptr, *pk, *pv, *pft, *pweff;
    if (!pq) {
        cudaGetSymbolAddress((void**)&pq, g_q);
        cudaGetSymbolAddress((void**)&pk, g_k);
        cudaGetSymbolAddress((void**)&pv, g_v);
        cudaGetSymbolAddress((void**)&pft, g_ft);
        cudaGetSymbolAddress((void**)&pweff, g_weff);
        cudaFuncSetAttribute(mma_gemm_k, cudaFuncAttributeMaxDynamicSharedMemorySize, SM_NEED);
    }

    zero_cnt_k<<<(NN + 255) / 256, 256>>>();
    weff_k<<<(INF_ * INF_ + 255) / 256, 256>>>(Wscale);

    const int MT = (NN + 127) / 128;  // 391 tiles
    mma_gemm_k<<<MT, 256, SM_NEED>>>(feature, Wq, nullptr, pq, NN);
    mma_gemm_k<<<MT, 256, SM_NEED>>>(feature, Wk, nullptr, pk, NN);
    mma_gemm_k<<<MT, 256, SM_NEED>>>(feature, Wv, nullptr, pv, NN);

    hist_k<<<(EE + 255) / 256, 256>>>(dst);
    scan_k<<<1, 1024>>>();
    scatter_k<<<(EE + 255) / 256, 256>>>(src, dst);

    agg_k<<<(NN * 32 + 255) / 256, 256>>>();

    mma_gemm_k<<<MT, 256, SM_NEED>>>(pft, pweff, feature, out, NN);
}